// round 7
// baseline (speedup 1.0000x reference)
#include <cuda_runtime.h>

#define SCALING 2.0f     // alpha / r = 32 / 16
#define TOK     16384

// scratch (allocation-free rule: __device__ globals)
__device__ float g_v[TOK * 32];   // per token: [ s*g1*ce[0:16] | s*g2*ce[0:16] ]
__device__ int   g_eidx[TOK];     // e1 | (e2 << 8)

static __device__ __forceinline__ unsigned long long ffma2(unsigned long long a,
                                                           unsigned long long b,
                                                           unsigned long long c) {
    unsigned long long d;
    asm("fma.rn.f32x2 %0, %1, %2, %3;" : "=l"(d) : "l"(a), "l"(b), "l"(c));
    return d;
}

union F4  { float4 f; unsigned long long u[2]; };
union U2F { unsigned long long u; float2 f; };

// ---------------------------------------------------------------------------
// Kernel 1: logits(8) + ce(16) + routing.  (unchanged from best-known config)
// CTA = 256 thr = 8 warps; warp = k-slice (128 k), lane = 2 tokens (lane,
// lane+32) of a 64-token group. Weights broadcast from smem; x double-
// buffered + swizzled; sred overlaid on x tile.
// ---------------------------------------------------------------------------
#define K1_SW_F4   6144                      // 24 rows * 256 f4
#define K1_XB_F4   2048                      // one buffer: 64 tok * 32 f4
#define K1_SMEM    ((K1_SW_F4 + 2 * K1_XB_F4) * 16)   // 163840 B

__global__ void __launch_bounds__(256, 1)
k_route(const float4* __restrict__ X4,   // x: row = 256 f4
        const float4* __restrict__ WR4,  // w_route: 2048 f4
        const float4* __restrict__ CP4,  // compress: 4096 f4
        int ngroups)                     // 64-token groups
{
    extern __shared__ float4 sm4[];
    float4* sW   = sm4;                       // [24][256]
    float4* sX   = sm4 + K1_SW_F4;            // 2 x [64][32] (swizzled)
    float*  sred = (float*)sX;                // overlay: [24][8][64] = 48KB

    const int tid   = threadIdx.x;
    const int lane  = tid & 31;
    const int ks    = tid >> 5;               // k-slice warp
    const int stok0 = tid >> 5;               // staging token = stok0 + 8j
    const int scol  = tid & 31;               // staging f4 col

    for (int i = tid; i < 2048; i += 256) sW[i]        = WR4[i];
    for (int i = tid; i < 4096; i += 256) sW[2048 + i] = CP4[i];

    for (int g = blockIdx.x; g < ngroups; g += gridDim.x) {
        const int tb = g * 64;
        float4 st[8];

        // prologue: chunk 0 -> buf 0  (sX safe: Sr3 of prev group passed)
        {
            const float4* xb = X4 + (size_t)tb * 256;
#pragma unroll
            for (int j = 0; j < 8; j++)
                st[j] = xb[(size_t)(stok0 + 8 * j) * 256 + scol];
#pragma unroll
            for (int j = 0; j < 8; j++) {
                int tok = stok0 + 8 * j;
                sX[tok * 32 + (scol ^ (tok & 31))] = st[j];
            }
        }
        __syncthreads();   // S1 (also covers sW on first group)

        unsigned long long acc[48];
#pragma unroll
        for (int o = 0; o < 48; o++) acc[o] = 0ull;

        for (int c = 0; c < 8; c++) {
            if (c < 7) {
                const float4* xb = X4 + (size_t)tb * 256 + (c + 1) * 32;
#pragma unroll
                for (int j = 0; j < 8; j++)
                    st[j] = xb[(size_t)(stok0 + 8 * j) * 256 + scol];
            }
            const float4* xbuf = sX + (c & 1) * K1_XB_F4;
            const float4* wb   = sW + c * 32 + ks * 4;
#pragma unroll
            for (int b = 0; b < 4; b++) {
                const int f4i = ks * 4 + b;
                F4 xa, xc;
                xa.f = xbuf[lane * 32 + (f4i ^ lane)];          // token lane
                xc.f = xbuf[(lane + 32) * 32 + (f4i ^ lane)];   // token lane+32
#pragma unroll
                for (int o = 0; o < 24; o++) {
                    F4 w; w.f = wb[o * 256 + b];                // broadcast
                    acc[o]      = ffma2(w.u[0], xa.u[0], acc[o]);
                    acc[o]      = ffma2(w.u[1], xa.u[1], acc[o]);
                    acc[24 + o] = ffma2(w.u[0], xc.u[0], acc[24 + o]);
                    acc[24 + o] = ffma2(w.u[1], xc.u[1], acc[24 + o]);
                }
            }
            if (c < 7) {
#pragma unroll
                for (int j = 0; j < 8; j++) {
                    int tok = stok0 + 8 * j;
                    sX[((c + 1) & 1) * K1_XB_F4 + tok * 32 + (scol ^ (tok & 31))] = st[j];
                }
                __syncthreads();
            }
        }
        __syncthreads();   // Sr1: all x reads done; sX reusable as sred

#pragma unroll
        for (int o = 0; o < 24; o++) {
            U2F ua, uc;
            ua.u = acc[o];      sred[o * 512 + ks * 64 + lane]      = ua.f.x + ua.f.y;
            uc.u = acc[24 + o]; sred[o * 512 + ks * 64 + lane + 32] = uc.f.x + uc.f.y;
        }
        __syncthreads();   // Sr2

        if (ks < 2) {      // warps 0,1: 64 tokens, finish reduce + route
            const int tok = ks * 32 + lane;
            float red[24];
#pragma unroll
            for (int o = 0; o < 24; o++) {
                float s = 0.f;
#pragma unroll
                for (int k8 = 0; k8 < 8; k8++) s += sred[o * 512 + k8 * 64 + tok];
                red[o] = s;
            }
            int e1 = 0; float v1 = red[0];
#pragma unroll
            for (int e = 1; e < 8; e++) if (red[e] > v1) { v1 = red[e]; e1 = e; }
            int e2 = 0; float v2 = -3.0e38f;
#pragma unroll
            for (int e = 0; e < 8; e++) if (e != e1 && red[e] > v2) { v2 = red[e]; e2 = e; }
            float ex  = __expf(v2 - v1);
            float inv = 1.0f / (1.0f + ex);
            float sg1 = SCALING * inv;
            float sg2 = SCALING * ex * inv;
            const int t = tb + tok;
            float4* vo = (float4*)(g_v + (size_t)t * 32);
#pragma unroll
            for (int j = 0; j < 4; j++)
                vo[j] = make_float4(sg1 * red[8 + j * 4], sg1 * red[9 + j * 4],
                                    sg1 * red[10 + j * 4], sg1 * red[11 + j * 4]);
#pragma unroll
            for (int j = 0; j < 4; j++)
                vo[4 + j] = make_float4(sg2 * red[8 + j * 4], sg2 * red[9 + j * 4],
                                        sg2 * red[10 + j * 4], sg2 * red[11 + j * 4]);
            g_eidx[t] = e1 | (e2 << 8);
        }
        __syncthreads();   // Sr3: sred reads done before next group's STS
    }
}

// ---------------------------------------------------------------------------
// Kernel 2 (v3): expert-major combine, warp-disjoint tokens.
// CTA = 64 tokens x 256 cols, 64 threads (2 warps).
// Warp w owns tokens [w*32, w*32+32) — both experts of each token -> no
// cross-warp races on sacc rows. Each thread covers 8 cols (all 256 cols per
// warp). Per expert: 32 LDG128 register-stationary weights, then stream that
// warp's token list with prefetched v and 8 independent FFMA2 chains.
// ---------------------------------------------------------------------------
#define K2T      64
#define K2_SMEM  (K2T*256*4 + K2T*32*4 + 2*8*32*4 + K2T*4 + 2*8*4)  // 76096 B

__global__ void __launch_bounds__(64)
k_combine(const float4* __restrict__ R4,   // routed: [8][1024][16] -> e*4096 + o*4
          float4* __restrict__ out4)       // out: row = 256 f4
{
    extern __shared__ float sm[];
    float* sacc  = sm;                       // [64][256]
    float* sv    = sm + K2T * 256;           // [64][32]
    int*   slist = (int*)(sv + K2T * 32);    // [2][8][32]
    int*   se    = slist + 2 * 8 * 32;       // [64]
    int*   scnt  = se + K2T;                 // [2][8]

    const int tid  = threadIdx.x;            // 0..63
    const int w    = tid >> 5;               // warp (token half)
    const int lane = tid & 31;
    const int cb   = blockIdx.x;             // 0..3
    const int t0   = blockIdx.y * K2T;

    se[tid] = g_eidx[t0 + tid];
    {
        const float4* vg = (const float4*)(g_v + (size_t)t0 * 32);
        float4* sv4 = (float4*)sv;
#pragma unroll
        for (int i = tid; i < K2T * 8; i += 64) sv4[i] = vg[i];
    }
    __syncthreads();   // se + sv visible

    if (lane == 0) {   // 2 builder threads (tid 0, 32): deterministic order
        int c[8] = {0,0,0,0,0,0,0,0};
        const int tbase = w * 32;
        for (int t = tbase; t < tbase + 32; t++) {
            int ee = se[t];
            int e1 = ee & 255, e2 = (ee >> 8) & 255;
            slist[(w * 8 + e1) * 32 + c[e1]++] = t;         // first-expert half
            slist[(w * 8 + e2) * 32 + c[e2]++] = t | 128;   // bit7 = second half
        }
#pragma unroll
        for (int e = 0; e < 8; e++) scnt[w * 8 + e] = c[e];
    } else {           // other 62 threads zero the accumulator tile
        float4 z = make_float4(0.f, 0.f, 0.f, 0.f);
        float4* sa4 = (float4*)sacc;
        int i0 = tid - ((tid >= 32) ? 2 : 1);               // dense 0..61
        for (int i = i0; i < K2T * 64; i += 62) sa4[i] = z;
    }
    __syncthreads();

    // thread's 8 cols: global cols cb*256 + lane*8 .. +7 (both warps same cols)
    float4* sacc4 = (float4*)sacc;
    for (int e = 0; e < 8; e++) {
        const int n = scnt[w * 8 + e];
        if (!n) continue;
        // weights: 8 cols x 16 r = 32 float4, contiguous 512B per thread
        F4 wt[32];
        const float4* W = R4 + (size_t)e * 4096 + (size_t)cb * 1024 + lane * 32;
#pragma unroll
        for (int j = 0; j < 32; j++) wt[j].f = W[j];

        const int* lst = slist + (w * 8 + e) * 32;
        int ent = lst[0];
        F4 vc[4];
        {
            const F4* v = (const F4*)(sv + (ent & 63) * 32 + ((ent & 128) >> 3));
            vc[0] = v[0]; vc[1] = v[1]; vc[2] = v[2]; vc[3] = v[3];
        }
        for (int k = 0; k < n; k++) {
            const int entn = (k + 1 < n) ? lst[k + 1] : ent;
            F4 vn[4];
            {   // prefetch next entry's v (broadcast LDS128 x4)
                const F4* v = (const F4*)(sv + (entn & 63) * 32 + ((entn & 128) >> 3));
                vn[0] = v[0]; vn[1] = v[1]; vn[2] = v[2]; vn[3] = v[3];
            }
            // 8 independent chains (one per col), 8 FFMA2 each
            float res[8];
#pragma unroll
            for (int c = 0; c < 8; c++) {
                unsigned long long a = 0ull;
#pragma unroll
                for (int q = 0; q < 4; q++) {
                    a = ffma2(wt[c * 4 + q].u[0], vc[q].u[0], a);
                    a = ffma2(wt[c * 4 + q].u[1], vc[q].u[1], a);
                }
                U2F u; u.u = a;
                res[c] = u.f.x + u.f.y;
            }
            // RMW: 2 float4 slots (exclusive: token half per warp, cols per thread)
            const int tl = ent & 63;
            float4* p = sacc4 + tl * 64 + lane * 2;
            float4 A = p[0], B = p[1];
            A.x += res[0]; A.y += res[1]; A.z += res[2]; A.w += res[3];
            B.x += res[4]; B.y += res[5]; B.z += res[6]; B.w += res[7];
            p[0] = A; p[1] = B;
            vc[0] = vn[0]; vc[1] = vn[1]; vc[2] = vn[2]; vc[3] = vn[3];
            ent = entn;
        }
    }
    __syncthreads();

#pragma unroll
    for (int i = tid; i < K2T * 64; i += 64) {
        int tl = i >> 6, c4 = i & 63;
        out4[(size_t)(t0 + tl) * 256 + cb * 64 + c4] = sacc4[i];
    }
}

// ---------------------------------------------------------------------------
// Launch. Inputs identified by element count (all distinct):
//   x = 16777216, w_route = 8192, compress = 16384, routed = 131072
// ---------------------------------------------------------------------------
extern "C" void kernel_launch(void* const* d_in, const int* in_sizes, int n_in,
                              void* d_out, int out_size) {
    const float *x = nullptr, *wr = nullptr, *cp = nullptr, *rt = nullptr;
    long long n_x = 0;
    for (int i = 0; i < n_in; i++) {
        int s = in_sizes[i];
        if      (s == 8192)   wr = (const float*)d_in[i];
        else if (s == 16384)  cp = (const float*)d_in[i];
        else if (s == 131072) rt = (const float*)d_in[i];
        else { x = (const float*)d_in[i]; n_x = s; }
    }
    const int n_tok = (int)(n_x / 1024);   // 16384

    cudaFuncSetAttribute(k_route,   cudaFuncAttributeMaxDynamicSharedMemorySize, K1_SMEM);
    cudaFuncSetAttribute(k_combine, cudaFuncAttributeMaxDynamicSharedMemorySize, K2_SMEM);

    k_route<<<148, 256, K1_SMEM>>>((const float4*)x, (const float4*)wr,
                                   (const float4*)cp, n_tok / 64);

    dim3 g2(4, n_tok / K2T);
    k_combine<<<g2, 64, K2_SMEM>>>((const float4*)rt, (float4*)d_out);
}

// round 8
// speedup vs baseline: 1.1928x; 1.1928x over previous
#include <cuda_runtime.h>

#define SCALING 2.0f     // alpha / r = 32 / 16
#define TOK     16384

// scratch (allocation-free rule: __device__ globals)
__device__ float g_v[TOK * 32];   // per token: [ s*g1*ce[0:16] | s*g2*ce[0:16] ]
__device__ int   g_eidx[TOK];     // e1 | (e2 << 8)

static __device__ __forceinline__ unsigned long long ffma2(unsigned long long a,
                                                           unsigned long long b,
                                                           unsigned long long c) {
    unsigned long long d;
    asm("fma.rn.f32x2 %0, %1, %2, %3;" : "=l"(d) : "l"(a), "l"(b), "l"(c));
    return d;
}

union F4  { float4 f; unsigned long long u[2]; };
union U2F { unsigned long long u; float2 f; };

// ---------------------------------------------------------------------------
// Kernel 1: logits(8) + ce(16) + routing.  (unchanged — best-known config)
// ---------------------------------------------------------------------------
#define K1_SW_F4   6144                      // 24 rows * 256 f4
#define K1_XB_F4   2048                      // one buffer: 64 tok * 32 f4
#define K1_SMEM    ((K1_SW_F4 + 2 * K1_XB_F4) * 16)   // 163840 B

__global__ void __launch_bounds__(256, 1)
k_route(const float4* __restrict__ X4,   // x: row = 256 f4
        const float4* __restrict__ WR4,  // w_route: 2048 f4
        const float4* __restrict__ CP4,  // compress: 4096 f4
        int ngroups)                     // 64-token groups
{
    extern __shared__ float4 sm4[];
    float4* sW   = sm4;                       // [24][256]
    float4* sX   = sm4 + K1_SW_F4;            // 2 x [64][32] (swizzled)
    float*  sred = (float*)sX;                // overlay: [24][8][64] = 48KB

    const int tid   = threadIdx.x;
    const int lane  = tid & 31;
    const int ks    = tid >> 5;               // k-slice warp
    const int stok0 = tid >> 5;               // staging token = stok0 + 8j
    const int scol  = tid & 31;               // staging f4 col

    for (int i = tid; i < 2048; i += 256) sW[i]        = WR4[i];
    for (int i = tid; i < 4096; i += 256) sW[2048 + i] = CP4[i];

    for (int g = blockIdx.x; g < ngroups; g += gridDim.x) {
        const int tb = g * 64;
        float4 st[8];

        {
            const float4* xb = X4 + (size_t)tb * 256;
#pragma unroll
            for (int j = 0; j < 8; j++)
                st[j] = xb[(size_t)(stok0 + 8 * j) * 256 + scol];
#pragma unroll
            for (int j = 0; j < 8; j++) {
                int tok = stok0 + 8 * j;
                sX[tok * 32 + (scol ^ (tok & 31))] = st[j];
            }
        }
        __syncthreads();   // S1 (also covers sW on first group)

        unsigned long long acc[48];
#pragma unroll
        for (int o = 0; o < 48; o++) acc[o] = 0ull;

        for (int c = 0; c < 8; c++) {
            if (c < 7) {
                const float4* xb = X4 + (size_t)tb * 256 + (c + 1) * 32;
#pragma unroll
                for (int j = 0; j < 8; j++)
                    st[j] = xb[(size_t)(stok0 + 8 * j) * 256 + scol];
            }
            const float4* xbuf = sX + (c & 1) * K1_XB_F4;
            const float4* wb   = sW + c * 32 + ks * 4;
#pragma unroll
            for (int b = 0; b < 4; b++) {
                const int f4i = ks * 4 + b;
                F4 xa, xc;
                xa.f = xbuf[lane * 32 + (f4i ^ lane)];          // token lane
                xc.f = xbuf[(lane + 32) * 32 + (f4i ^ lane)];   // token lane+32
#pragma unroll
                for (int o = 0; o < 24; o++) {
                    F4 w; w.f = wb[o * 256 + b];                // broadcast
                    acc[o]      = ffma2(w.u[0], xa.u[0], acc[o]);
                    acc[o]      = ffma2(w.u[1], xa.u[1], acc[o]);
                    acc[24 + o] = ffma2(w.u[0], xc.u[0], acc[24 + o]);
                    acc[24 + o] = ffma2(w.u[1], xc.u[1], acc[24 + o]);
                }
            }
            if (c < 7) {
#pragma unroll
                for (int j = 0; j < 8; j++) {
                    int tok = stok0 + 8 * j;
                    sX[((c + 1) & 1) * K1_XB_F4 + tok * 32 + (scol ^ (tok & 31))] = st[j];
                }
                __syncthreads();
            }
        }
        __syncthreads();   // Sr1: all x reads done; sX reusable as sred

#pragma unroll
        for (int o = 0; o < 24; o++) {
            U2F ua, uc;
            ua.u = acc[o];      sred[o * 512 + ks * 64 + lane]      = ua.f.x + ua.f.y;
            uc.u = acc[24 + o]; sred[o * 512 + ks * 64 + lane + 32] = uc.f.x + uc.f.y;
        }
        __syncthreads();   // Sr2

        if (ks < 2) {      // warps 0,1: 64 tokens, finish reduce + route
            const int tok = ks * 32 + lane;
            float red[24];
#pragma unroll
            for (int o = 0; o < 24; o++) {
                float s = 0.f;
#pragma unroll
                for (int k8 = 0; k8 < 8; k8++) s += sred[o * 512 + k8 * 64 + tok];
                red[o] = s;
            }
            int e1 = 0; float v1 = red[0];
#pragma unroll
            for (int e = 1; e < 8; e++) if (red[e] > v1) { v1 = red[e]; e1 = e; }
            int e2 = 0; float v2 = -3.0e38f;
#pragma unroll
            for (int e = 0; e < 8; e++) if (e != e1 && red[e] > v2) { v2 = red[e]; e2 = e; }
            float ex  = __expf(v2 - v1);
            float inv = 1.0f / (1.0f + ex);
            float sg1 = SCALING * inv;
            float sg2 = SCALING * ex * inv;
            const int t = tb + tok;
            float4* vo = (float4*)(g_v + (size_t)t * 32);
#pragma unroll
            for (int j = 0; j < 4; j++)
                vo[j] = make_float4(sg1 * red[8 + j * 4], sg1 * red[9 + j * 4],
                                    sg1 * red[10 + j * 4], sg1 * red[11 + j * 4]);
#pragma unroll
            for (int j = 0; j < 4; j++)
                vo[4 + j] = make_float4(sg2 * red[8 + j * 4], sg2 * red[9 + j * 4],
                                        sg2 * red[10 + j * 4], sg2 * red[11 + j * 4]);
            g_eidx[t] = e1 | (e2 << 8);
        }
        __syncthreads();   // Sr3: sred reads done before next group's STS
    }
}

// ---------------------------------------------------------------------------
// Kernel 2 (v4): expert-major combine.
// CTA = 64 tokens x 256 cols, 128 threads (4 warps).
// Warp w owns col quarter [w*64, w*64+64); thread owns 2 ADJACENT cols.
// All warps stream the same per-expert entry lists (128 entries total);
// weights register-stationary, loaded by exactly one warp each (no dup);
// dense float2 smem RMW; sacc warp-disjoint by column -> race-free.
// ---------------------------------------------------------------------------
#define K2T      64
#define K2_SMEM  (K2T*256*4 + K2T*32*4 + 8*K2T*4 + K2T*4 + 8*4)   // 76064 B

__global__ void __launch_bounds__(128)
k_combine(const float4* __restrict__ R4,   // routed: [8][1024][16] -> e*4096 + o*4
          float4* __restrict__ out4)       // out: row = 256 f4
{
    extern __shared__ float sm[];
    float* sacc  = sm;                      // [64][256]
    float* sv    = sm + K2T * 256;          // [64][32]
    int*   slist = (int*)(sv + K2T * 32);   // [8][64]
    int*   se    = slist + 8 * K2T;         // [64]
    int*   scnt  = se + K2T;                // [8]

    const int tid  = threadIdx.x;           // 0..127
    const int w    = tid >> 5;              // col quarter
    const int lane = tid & 31;
    const int cb   = blockIdx.x;            // 0..3
    const int t0   = blockIdx.y * K2T;

    if (tid < K2T) se[tid] = g_eidx[t0 + tid];
    {
        const float4* vg = (const float4*)(g_v + (size_t)t0 * 32);
        float4* sv4 = (float4*)sv;
#pragma unroll
        for (int i = tid; i < K2T * 8; i += 128) sv4[i] = vg[i];
    }
    __syncthreads();

    if (tid == 0) {                         // serial -> deterministic order
        int c[8] = {0,0,0,0,0,0,0,0};
        for (int t = 0; t < K2T; t++) {
            int ee = se[t];
            int e1 = ee & 255, e2 = (ee >> 8) & 255;
            slist[e1 * K2T + c[e1]++] = t;
            slist[e2 * K2T + c[e2]++] = t | K2T;   // bit6 = second-expert half
        }
#pragma unroll
        for (int e = 0; e < 8; e++) scnt[e] = c[e];
    } else {                                // 127 threads zero sacc
        float4 z = make_float4(0.f, 0.f, 0.f, 0.f);
        float4* sa4 = (float4*)sacc;
        for (int i = tid - 1; i < K2T * 64; i += 127) sa4[i] = z;
    }
    __syncthreads();

    const int cl = w * 64 + lane * 2;       // local col pair (cl, cl+1)
    float2* sacc2 = (float2*)sacc;
    for (int e = 0; e < 8; e++) {
        const int n = scnt[e];
        if (!n) continue;
        // weights for 2 cols x 16 r = 8 contiguous float4 (128B per thread)
        F4 wt[8];
        const float4* W = R4 + (size_t)e * 4096 + (size_t)(cb * 256 + cl) * 4;
#pragma unroll
        for (int j = 0; j < 8; j++) wt[j].f = W[j];

        const int* lst = slist + e * K2T;
        int ent = lst[0];
        F4 vc[4];
        {
            const F4* v = (const F4*)(sv + (ent & 63) * 32 + ((ent & K2T) >> 2));
            vc[0] = v[0]; vc[1] = v[1]; vc[2] = v[2]; vc[3] = v[3];
        }
        for (int k = 0; k < n; k++) {
            const int entn = (k + 1 < n) ? lst[k + 1] : ent;
            F4 vn_[4];
            {   // prefetch next entry's v (broadcast LDS128 x4)
                const F4* v = (const F4*)(sv + (entn & 63) * 32 + ((entn & K2T) >> 2));
                vn_[0] = v[0]; vn_[1] = v[1]; vn_[2] = v[2]; vn_[3] = v[3];
            }
            unsigned long long a0 = 0ull, a1 = 0ull;   // 2 chains, 8 deep
#pragma unroll
            for (int q = 0; q < 4; q++) {
                a0 = ffma2(wt[q].u[0],     vc[q].u[0], a0);
                a0 = ffma2(wt[q].u[1],     vc[q].u[1], a0);
                a1 = ffma2(wt[4 + q].u[0], vc[q].u[0], a1);
                a1 = ffma2(wt[4 + q].u[1], vc[q].u[1], a1);
            }
            U2F u0, u1; u0.u = a0; u1.u = a1;
            const int tl = ent & 63;
            float2* p = sacc2 + tl * 128 + (cl >> 1);  // dense 8B stride/warp
            float2 A = *p;
            A.x += u0.f.x + u0.f.y;
            A.y += u1.f.x + u1.f.y;
            *p = A;
            vc[0] = vn_[0]; vc[1] = vn_[1]; vc[2] = vn_[2]; vc[3] = vn_[3];
            ent = entn;
        }
    }
    __syncthreads();

#pragma unroll
    for (int i = tid; i < K2T * 64; i += 128) {
        int tl = i >> 6, c4 = i & 63;
        out4[(size_t)(t0 + tl) * 256 + cb * 64 + c4] =
            ((const float4*)sacc)[i];
    }
}

// ---------------------------------------------------------------------------
// Launch. Inputs identified by element count (all distinct):
//   x = 16777216, w_route = 8192, compress = 16384, routed = 131072
// ---------------------------------------------------------------------------
extern "C" void kernel_launch(void* const* d_in, const int* in_sizes, int n_in,
                              void* d_out, int out_size) {
    const float *x = nullptr, *wr = nullptr, *cp = nullptr, *rt = nullptr;
    long long n_x = 0;
    for (int i = 0; i < n_in; i++) {
        int s = in_sizes[i];
        if      (s == 8192)   wr = (const float*)d_in[i];
        else if (s == 16384)  cp = (const float*)d_in[i];
        else if (s == 131072) rt = (const float*)d_in[i];
        else { x = (const float*)d_in[i]; n_x = s; }
    }
    const int n_tok = (int)(n_x / 1024);   // 16384

    cudaFuncSetAttribute(k_route,   cudaFuncAttributeMaxDynamicSharedMemorySize, K1_SMEM);
    cudaFuncSetAttribute(k_combine, cudaFuncAttributeMaxDynamicSharedMemorySize, K2_SMEM);

    k_route<<<148, 256, K1_SMEM>>>((const float4*)x, (const float4*)wr,
                                   (const float4*)cp, n_tok / 64);

    dim3 g2(4, n_tok / K2T);
    k_combine<<<g2, 128, K2_SMEM>>>((const float4*)rt, (float4*)d_out);
}